// round 12
// baseline (speedup 1.0000x reference)
#include <cuda_runtime.h>
#include <stdint.h>

#define NC    1000      // num classes
#define D4    256       // feature dim in float4 (1024 floats)
#define BQ    32768     // labels per batch (samples = 2*BQ rows of x)
#define MAXK  1024      // per-class index capacity (Poisson mean ~33)
#define TH    38        // target part size
#define EXTRA 184       // extra part slots
#define GRID  (NC + EXTRA)            // 1184 = 8 blocks/SM x 148 SMs (one wave)
#define LPB   ((BQ + GRID - 1) / GRID) // 28 labels per block in phase A

// ---- scratch (device globals; zero at load; reset discipline below) ----
__device__ int   g_counts[NC];
__device__ int   g_nparts[NC];       // effective parts per class
__device__ int4  g_plan[GRID];       // per-slot {c, lo, n, cnt}
__device__ int   g_idx[NC * MAXK];
__device__ float g_sum[NC * 1024];   // split-class partial sums (RED.ADD)
__device__ int   g_done2[NC];        // parts finished per split class
__device__ int   g_bar1;             // phase-A arrival counter
__device__ int   g_go;               // plan-ready flag
__device__ float g_loss;
__device__ int   g_present;
__device__ int   g_done;

// ---------------------------------------------------------------------------
// fused epilogue: mean + EMA + normalize + loss (R2/R11-proven)
// ---------------------------------------------------------------------------
__device__ __forceinline__ void epilogue(
        int c, int cnt, int t, float4 a, float4 b,
        const float4* __restrict__ ci4, const float4* __restrict__ cs4,
        float* sred) {
    const float s = 0.1f / (2.0f * (float)cnt);    // (1-mom)/count
    float4 cia = ci4[c * D4 + t];
    float4 cib = ci4[c * D4 + t + 128];
    float4 ua, ub;
    ua.x = cia.x * 0.9f + a.x * s;  ua.y = cia.y * 0.9f + a.y * s;
    ua.z = cia.z * 0.9f + a.z * s;  ua.w = cia.w * 0.9f + a.w * s;
    ub.x = cib.x * 0.9f + b.x * s;  ub.y = cib.y * 0.9f + b.y * s;
    ub.z = cib.z * 0.9f + b.z * s;  ub.w = cib.w * 0.9f + b.w * s;

    float nsq = ua.x*ua.x + ua.y*ua.y + ua.z*ua.z + ua.w*ua.w
              + ub.x*ub.x + ub.y*ub.y + ub.z*ub.z + ub.w*ub.w;
    #pragma unroll
    for (int o = 16; o; o >>= 1) nsq += __shfl_down_sync(0xffffffffu, nsq, o);
    if ((t & 31) == 0) sred[t >> 5] = nsq;
    __syncthreads();
    float rnorm = rsqrtf(sred[0] + sred[1] + sred[2] + sred[3]);

    float4 csa = cs4[c * D4 + t];
    float4 csb = cs4[c * D4 + t + 128];
    float dx = ua.x * rnorm - csa.x, dy = ua.y * rnorm - csa.y;
    float dz = ua.z * rnorm - csa.z, dw = ua.w * rnorm - csa.w;
    float ls = dx*dx + dy*dy + dz*dz + dw*dw;
    dx = ub.x * rnorm - csb.x; dy = ub.y * rnorm - csb.y;
    dz = ub.z * rnorm - csb.z; dw = ub.w * rnorm - csb.w;
    ls += dx*dx + dy*dy + dz*dz + dw*dw;
    #pragma unroll
    for (int o = 16; o; o >>= 1) ls += __shfl_down_sync(0xffffffffu, ls, o);
    __syncthreads();                          // protect sred reuse
    if ((t & 31) == 0) sred[t >> 5] = ls;
    __syncthreads();
    if (t == 0) {
        atomicAdd(&g_loss, sred[0] + sred[1] + sred[2] + sred[3]);
        atomicAdd(&g_present, 1);
    }
}

// ---------------------------------------------------------------------------
// single fused persistent kernel: scatter -> barrier -> plan -> gather/loss
//  Residency: 1184 blocks = exactly one wave (launch_bounds(128,8) => 64 regs
//  => 8 blocks/SM on 148 SMs), so the spin barrier is deadlock-free.
// ---------------------------------------------------------------------------
__global__ void __launch_bounds__(128, 8)
k_all(const float4* __restrict__ x4,
      const float4* __restrict__ ci4,
      const float4* __restrict__ cs4,
      const int* __restrict__ l32,
      const long long* __restrict__ l64,
      float* __restrict__ out) {
    const int t = threadIdx.x;
    const int b = blockIdx.x;
    __shared__ int   sidx[MAXK];
    __shared__ float sred[4];
    __shared__ int   sflag;
    __shared__ int   sh_shift;
    __shared__ int   s_wsum[4];

    // ---- label-width probe (warp 0): int32 labels read as int64 pack two
    //  labels; high word in [0,1000) with prob 1/1000 -> P(misdetect)~0 ----
    if (t < 32) {
        int ok = 1;
        #pragma unroll
        for (int k = t; k < 64; k += 32) {
            long long v = l64[k];
            if (v < 0 || v >= NC) ok = 0;
        }
        unsigned m = __ballot_sync(0xffffffffu, ok);
        if (t == 0) sh_shift = (m == 0xffffffffu) ? 1 : 0;
    }
    __syncthreads();

    // ---- phase A: scatter this block's label slice ----
    {
        const int j = b * LPB + t;
        if (t < LPB && j < BQ) {
            int c = l32[j << sh_shift];
            if ((unsigned)c < (unsigned)NC) {
                int pos = atomicAdd(&g_counts[c], 1);
                if (pos < MAXK) g_idx[c * MAXK + pos] = j;
            }
        }
    }
    __syncthreads();
    if (t == 0) { __threadfence(); atomicAdd(&g_bar1, 1); }

    // ---- barrier + planning ----
    if (b == 0) {
        if (t == 0) {
            while (((volatile int*)&g_bar1)[0] < GRID) __nanosleep(32);
        }
        __syncthreads();
        __threadfence();

        // each thread owns 8 consecutive classes: [t*8, t*8+8)
        int cnts[8], nps[8];
        int esum = 0;
        const int c0 = t * 8;
        #pragma unroll
        for (int i = 0; i < 8; i++) {
            int c = c0 + i;
            int cnt = (c < NC) ? g_counts[c] : 0;
            if (cnt > MAXK) cnt = MAXK;
            cnts[i] = cnt;
            int np = (cnt > TH) ? (cnt + TH - 1) / TH : 1;
            nps[i] = np;
            esum += np - 1;
        }
        // exclusive prefix of extras across 128 threads
        const int lane = t & 31, w = t >> 5;
        int v = esum;
        #pragma unroll
        for (int o = 1; o < 32; o <<= 1) {
            int u = __shfl_up_sync(0xffffffffu, v, o);
            if (lane >= o) v += u;
        }
        if (lane == 31) s_wsum[w] = v;
        __syncthreads();
        int wbase = 0;
        #pragma unroll
        for (int i = 0; i < 4; i++) if (i < w) wbase += s_wsum[i];
        int run = wbase + v - esum;            // exclusive prefix for class c0
        const int totE = s_wsum[0] + s_wsum[1] + s_wsum[2] + s_wsum[3];

        #pragma unroll
        for (int i = 0; i < 8; i++) {
            int c = c0 + i;
            if (c >= NC) break;
            const int cnt = cnts[i];
            const int np  = nps[i];
            int pe = run < EXTRA ? run : EXTRA;
            int allowed = np - 1;
            if (allowed > EXTRA - pe) allowed = EXTRA - pe;
            const int npe = 1 + allowed;
            g_nparts[c] = npe;
            g_counts[c] = 0;                   // reset for next replay
            // part 0 at slot c
            int hi0 = cnt / npe;               // lo=0
            g_plan[c] = make_int4(c, 0, hi0, cnt);
            // extra parts at slots NC + pe + k
            for (int k = 0; k < allowed; k++) {
                int p  = k + 1;
                int lo = (cnt * p) / npe;
                int hi = (cnt * (p + 1)) / npe;
                g_plan[NC + pe + k] = make_int4(c, lo, hi - lo, cnt);
            }
            run += np - 1;
        }
        // null-fill leftover slots
        int totEc = totE < EXTRA ? totE : EXTRA;
        for (int s2 = NC + totEc + t; s2 < GRID; s2 += 128)
            g_plan[s2] = make_int4(0, 0, 0, 0);

        __threadfence();
        __syncthreads();
        if (t == 0) ((volatile int*)&g_go)[0] = 1;
    } else {
        if (t == 0) {
            while (((volatile int*)&g_go)[0] == 0) __nanosleep(32);
        }
    }
    __syncthreads();
    __threadfence();

    // ---- phase B: gather / reduce / loss (R11-proven hot path) ----
    const int4 pl = g_plan[b];
    const int c   = pl.x;
    const int lo  = pl.y;
    const int n   = pl.z;
    const int cnt = pl.w;

    if (n > 0) {
        for (int k = t; k < n; k += 128) sidx[k] = g_idx[c * MAXK + lo + k];
        __syncthreads();

        const float4* xa = x4 + t;          // float4 column t
        const float4* xb = x4 + t + 128;    // float4 column t+128
        float4 aA = make_float4(0.f,0.f,0.f,0.f);
        float4 bA = make_float4(0.f,0.f,0.f,0.f);
        float4 aB = make_float4(0.f,0.f,0.f,0.f);
        float4 bB = make_float4(0.f,0.f,0.f,0.f);

        int k = 0;
        for (; k + 2 <= n; k += 2) {
            int j0 = sidx[k], j1 = sidx[k + 1];
            float4 p0 = __ldcs(xa + (size_t)j0 * D4);
            float4 q0 = __ldcs(xb + (size_t)j0 * D4);
            float4 p1 = __ldcs(xa + (size_t)(j0 + BQ) * D4);
            float4 q1 = __ldcs(xb + (size_t)(j0 + BQ) * D4);
            float4 p2 = __ldcs(xa + (size_t)j1 * D4);
            float4 q2 = __ldcs(xb + (size_t)j1 * D4);
            float4 p3 = __ldcs(xa + (size_t)(j1 + BQ) * D4);
            float4 q3 = __ldcs(xb + (size_t)(j1 + BQ) * D4);
            aA.x += p0.x + p1.x; aA.y += p0.y + p1.y; aA.z += p0.z + p1.z; aA.w += p0.w + p1.w;
            bA.x += q0.x + q1.x; bA.y += q0.y + q1.y; bA.z += q0.z + q1.z; bA.w += q0.w + q1.w;
            aB.x += p2.x + p3.x; aB.y += p2.y + p3.y; aB.z += p2.z + p3.z; aB.w += p2.w + p3.w;
            bB.x += q2.x + q3.x; bB.y += q2.y + q3.y; bB.z += q2.z + q3.z; bB.w += q2.w + q3.w;
        }
        if (k < n) {
            int j0 = sidx[k];
            float4 p0 = __ldcs(xa + (size_t)j0 * D4);
            float4 q0 = __ldcs(xb + (size_t)j0 * D4);
            float4 p1 = __ldcs(xa + (size_t)(j0 + BQ) * D4);
            float4 q1 = __ldcs(xb + (size_t)(j0 + BQ) * D4);
            aA.x += p0.x + p1.x; aA.y += p0.y + p1.y; aA.z += p0.z + p1.z; aA.w += p0.w + p1.w;
            bA.x += q0.x + q1.x; bA.y += q0.y + q1.y; bA.z += q0.z + q1.z; bA.w += q0.w + q1.w;
        }
        aA.x += aB.x; aA.y += aB.y; aA.z += aB.z; aA.w += aB.w;
        bA.x += bB.x; bA.y += bB.y; bA.z += bB.z; bA.w += bB.w;

        if (n == cnt) {
            // ---- unsplit: register epilogue, no global sums ----
            epilogue(c, cnt, t, aA, bA, ci4, cs4, sred);
        } else {
            // ---- split: one post-loop RED.ADD batch + completer ----
            float* gs = g_sum + (size_t)c * 1024;
            atomicAdd(gs + 4 * t + 0,   aA.x);
            atomicAdd(gs + 4 * t + 1,   aA.y);
            atomicAdd(gs + 4 * t + 2,   aA.z);
            atomicAdd(gs + 4 * t + 3,   aA.w);
            atomicAdd(gs + 4 * t + 512, bA.x);
            atomicAdd(gs + 4 * t + 513, bA.y);
            atomicAdd(gs + 4 * t + 514, bA.z);
            atomicAdd(gs + 4 * t + 515, bA.w);
            __threadfence();
            __syncthreads();
            if (t == 0) {
                int np  = g_nparts[c];
                int old = atomicAdd(&g_done2[c], 1);
                sflag = (old == np - 1);
                if (sflag) g_done2[c] = 0;        // reset for replay
            }
            __syncthreads();
            if (sflag) {
                float4 sa = __ldcg((const float4*)gs + t);
                float4 sb = __ldcg((const float4*)gs + t + 128);
                ((float4*)gs)[t]       = make_float4(0.f,0.f,0.f,0.f);
                ((float4*)gs)[t + 128] = make_float4(0.f,0.f,0.f,0.f);
                epilogue(c, cnt, t, sa, sb, ci4, cs4, sred);
            }
        }
    }

    // ---- chip-level finalize: all GRID blocks arrive ----
    if (t == 0) {
        __threadfence();
        if (atomicAdd(&g_done, 1) == GRID - 1) {
            float L  = atomicAdd(&g_loss, 0.0f);       // L2-coherent read
            int   np = atomicAdd(&g_present, 0);
            out[0] = L / (float)(np > 0 ? np : 1);
            g_done = 0; g_loss = 0.0f; g_present = 0;  // reset for replay
            g_bar1 = 0; g_go = 0;
            __threadfence();
        }
    }
}

extern "C" void kernel_launch(void* const* d_in, const int* in_sizes, int n_in,
                              void* d_out, int out_size) {
    const float4* x4  = (const float4*)d_in[0];
    const float4* ci4 = (const float4*)d_in[1];
    const float4* cs4 = (const float4*)d_in[2];
    const void*   l   = d_in[3];

    k_all<<<GRID, 128>>>(x4, ci4, cs4,
                         (const int*)l, (const long long*)l, (float*)d_out);
}

// round 15
// speedup vs baseline: 1.0481x; 1.0481x over previous
#include <cuda_runtime.h>
#include <stdint.h>

#define NC    1000      // num classes
#define D4    256       // feature dim in float4 (1024 floats)
#define BQ    32768     // labels per batch (samples = 2*BQ rows of x)
#define MAXK  1024      // per-class index capacity (Poisson mean ~33)
#define TH    38        // target part size (split classes with cnt > TH)
#define EXTRA 184       // extra part slots
#define GRID  (NC + EXTRA)   // 1184 = one full wave at 8 blocks/SM x 148 SMs

// ---- scratch (device globals; zero at load; reset discipline below) ----
__device__ int   g_counts[NC];
__device__ int   g_nparts[NC];       // effective parts per class
__device__ int4  g_plan[GRID];       // per-slot {c, lo, n, cnt}
__device__ int   g_idx[NC * MAXK];
__device__ float g_sum[NC * 1024];   // split-class partial sums (RED.ADD)
__device__ int   g_done2[NC];        // parts finished per split class
__device__ int   g_sdone;
__device__ float g_loss;
__device__ int   g_present;
__device__ int   g_done;

// ---------------------------------------------------------------------------
// K1: counting-sort scatter + last-block plan via atomic slot-grab.
//  Label-width probe: reading int32 labels as int64 packs two labels; the
//  high word lands in [0,1000) with prob 1/1000 per pair -> P(misdetect)~0.
//  Planning needs no prefix scan: extra-slot order is irrelevant, so each
//  split class grabs its slots with one shared atomicAdd (3 barriers total).
// ---------------------------------------------------------------------------
__global__ void k_scatter(const int* __restrict__ l32,
                          const long long* __restrict__ l64) {
    __shared__ int sh_shift;
    __shared__ int s_last;
    __shared__ int s_extra;
    const int t = threadIdx.x;
    if (t < 32) {
        int ok = 1;
        #pragma unroll
        for (int k = t; k < 64; k += 32) {
            long long v = l64[k];
            if (v < 0 || v >= NC) ok = 0;
        }
        unsigned m = __ballot_sync(0xffffffffu, ok);
        if (t == 0) sh_shift = (m == 0xffffffffu) ? 1 : 0;
    }
    __syncthreads();
    const int shift = sh_shift;
    const int j = blockIdx.x * 1024 + t;      // 32 blocks x 1024 threads
    int c = l32[j << shift];
    if ((unsigned)c < (unsigned)NC) {
        int pos = atomicAdd(&g_counts[c], 1);
        if (pos < MAXK) g_idx[c * MAXK + pos] = j;
    }

    // ---- elect last block ----
    __syncthreads();
    if (t == 0) {
        __threadfence();
        s_last = (atomicAdd(&g_sdone, 1) == (int)gridDim.x - 1);
        s_extra = 0;
    }
    __syncthreads();
    if (!s_last) return;

    // ---- plan: one thread per class, atomic slot-grab for extras ----
    if (t < NC) {
        int cnt = g_counts[t];
        if (cnt > MAXK) cnt = MAXK;
        g_counts[t] = 0;                      // reset for next replay
        int want = (cnt > TH) ? (cnt + TH - 1) / TH - 1 : 0;
        int base = 0;
        if (want > 0) base = atomicAdd(&s_extra, want);
        int allowed = want;
        if (base >= EXTRA) allowed = 0;
        else if (allowed > EXTRA - base) allowed = EXTRA - base;
        const int npe = 1 + allowed;
        g_nparts[t] = npe;
        g_plan[t] = make_int4(t, 0, cnt / npe, cnt);       // part 0 at slot t
        for (int k = 0; k < allowed; k++) {
            int p  = k + 1;
            int lo = (cnt * p) / npe;
            int hi = (cnt * (p + 1)) / npe;
            g_plan[NC + base + k] = make_int4(t, lo, hi - lo, cnt);
        }
    }
    __syncthreads();
    int tot = s_extra;
    if (tot > EXTRA) tot = EXTRA;
    for (int s2 = NC + tot + t; s2 < GRID; s2 += 1024)
        g_plan[s2] = make_int4(0, 0, 0, 0);   // null parts
    if (t == 0) g_sdone = 0;                  // reset for next replay
}

// ---------------------------------------------------------------------------
// fused epilogue: mean + EMA + normalize + loss (R2/R11-proven)
// ---------------------------------------------------------------------------
__device__ __forceinline__ void epilogue(
        int c, int cnt, int t, float4 a, float4 b,
        const float4* __restrict__ ci4, const float4* __restrict__ cs4,
        float* sred) {
    const float s = 0.1f / (2.0f * (float)cnt);    // (1-mom)/count
    float4 cia = ci4[c * D4 + t];
    float4 cib = ci4[c * D4 + t + 128];
    float4 ua, ub;
    ua.x = cia.x * 0.9f + a.x * s;  ua.y = cia.y * 0.9f + a.y * s;
    ua.z = cia.z * 0.9f + a.z * s;  ua.w = cia.w * 0.9f + a.w * s;
    ub.x = cib.x * 0.9f + b.x * s;  ub.y = cib.y * 0.9f + b.y * s;
    ub.z = cib.z * 0.9f + b.z * s;  ub.w = cib.w * 0.9f + b.w * s;

    float nsq = ua.x*ua.x + ua.y*ua.y + ua.z*ua.z + ua.w*ua.w
              + ub.x*ub.x + ub.y*ub.y + ub.z*ub.z + ub.w*ub.w;
    #pragma unroll
    for (int o = 16; o; o >>= 1) nsq += __shfl_down_sync(0xffffffffu, nsq, o);
    if ((t & 31) == 0) sred[t >> 5] = nsq;
    __syncthreads();
    float rnorm = rsqrtf(sred[0] + sred[1] + sred[2] + sred[3]);

    float4 csa = cs4[c * D4 + t];
    float4 csb = cs4[c * D4 + t + 128];
    float dx = ua.x * rnorm - csa.x, dy = ua.y * rnorm - csa.y;
    float dz = ua.z * rnorm - csa.z, dw = ua.w * rnorm - csa.w;
    float ls = dx*dx + dy*dy + dz*dz + dw*dw;
    dx = ub.x * rnorm - csb.x; dy = ub.y * rnorm - csb.y;
    dz = ub.z * rnorm - csb.z; dw = ub.w * rnorm - csb.w;
    ls += dx*dx + dy*dy + dz*dz + dw*dw;
    #pragma unroll
    for (int o = 16; o; o >>= 1) ls += __shfl_down_sync(0xffffffffu, ls, o);
    __syncthreads();                          // protect sred reuse
    if ((t & 31) == 0) sred[t >> 5] = ls;
    __syncthreads();
    if (t == 0) {
        atomicAdd(&g_loss, sred[0] + sred[1] + sred[2] + sred[3]);
        atomicAdd(&g_present, 1);
    }
}

// ---------------------------------------------------------------------------
// K2: R11-proven hot path, plan-driven. 1184 blocks x 128 threads, one wave.
//  Startup: ONE int4 load -> index staging -> stream. Unsplit class: pure
//  register path. Split class: post-loop RED.ADD batch + completer epilogue.
// ---------------------------------------------------------------------------
__global__ void __launch_bounds__(128, 8)
k_main(const float4* __restrict__ x4,
       const float4* __restrict__ ci4,
       const float4* __restrict__ cs4,
       float* __restrict__ out) {
    const int t = threadIdx.x;
    __shared__ int   sidx[MAXK];
    __shared__ float sred[4];
    __shared__ int   sflag;

    const int4 pl = g_plan[blockIdx.x];
    const int c   = pl.x;
    const int lo  = pl.y;
    const int n   = pl.z;
    const int cnt = pl.w;

    if (n > 0) {
        for (int k = t; k < n; k += 128) sidx[k] = g_idx[c * MAXK + lo + k];
        __syncthreads();

        const float4* xa = x4 + t;          // float4 column t
        const float4* xb = x4 + t + 128;    // float4 column t+128
        float4 aA = make_float4(0.f,0.f,0.f,0.f);
        float4 bA = make_float4(0.f,0.f,0.f,0.f);
        float4 aB = make_float4(0.f,0.f,0.f,0.f);
        float4 bB = make_float4(0.f,0.f,0.f,0.f);

        int k = 0;
        for (; k + 2 <= n; k += 2) {
            int j0 = sidx[k], j1 = sidx[k + 1];
            float4 p0 = __ldcs(xa + (size_t)j0 * D4);
            float4 q0 = __ldcs(xb + (size_t)j0 * D4);
            float4 p1 = __ldcs(xa + (size_t)(j0 + BQ) * D4);
            float4 q1 = __ldcs(xb + (size_t)(j0 + BQ) * D4);
            float4 p2 = __ldcs(xa + (size_t)j1 * D4);
            float4 q2 = __ldcs(xb + (size_t)j1 * D4);
            float4 p3 = __ldcs(xa + (size_t)(j1 + BQ) * D4);
            float4 q3 = __ldcs(xb + (size_t)(j1 + BQ) * D4);
            aA.x += p0.x + p1.x; aA.y += p0.y + p1.y; aA.z += p0.z + p1.z; aA.w += p0.w + p1.w;
            bA.x += q0.x + q1.x; bA.y += q0.y + q1.y; bA.z += q0.z + q1.z; bA.w += q0.w + q1.w;
            aB.x += p2.x + p3.x; aB.y += p2.y + p3.y; aB.z += p2.z + p3.z; aB.w += p2.w + p3.w;
            bB.x += q2.x + q3.x; bB.y += q2.y + q3.y; bB.z += q2.z + q3.z; bB.w += q2.w + q3.w;
        }
        if (k < n) {
            int j0 = sidx[k];
            float4 p0 = __ldcs(xa + (size_t)j0 * D4);
            float4 q0 = __ldcs(xb + (size_t)j0 * D4);
            float4 p1 = __ldcs(xa + (size_t)(j0 + BQ) * D4);
            float4 q1 = __ldcs(xb + (size_t)(j0 + BQ) * D4);
            aA.x += p0.x + p1.x; aA.y += p0.y + p1.y; aA.z += p0.z + p1.z; aA.w += p0.w + p1.w;
            bA.x += q0.x + q1.x; bA.y += q0.y + q1.y; bA.z += q0.z + q1.z; bA.w += q0.w + q1.w;
        }
        aA.x += aB.x; aA.y += aB.y; aA.z += aB.z; aA.w += aB.w;
        bA.x += bB.x; bA.y += bB.y; bA.z += bB.z; bA.w += bB.w;

        if (n == cnt) {
            // ---- unsplit: register epilogue, no global sums ----
            epilogue(c, cnt, t, aA, bA, ci4, cs4, sred);
        } else {
            // ---- split: one post-loop RED.ADD batch + completer ----
            float* gs = g_sum + (size_t)c * 1024;
            atomicAdd(gs + 4 * t + 0,   aA.x);
            atomicAdd(gs + 4 * t + 1,   aA.y);
            atomicAdd(gs + 4 * t + 2,   aA.z);
            atomicAdd(gs + 4 * t + 3,   aA.w);
            atomicAdd(gs + 4 * t + 512, bA.x);
            atomicAdd(gs + 4 * t + 513, bA.y);
            atomicAdd(gs + 4 * t + 514, bA.z);
            atomicAdd(gs + 4 * t + 515, bA.w);
            __threadfence();
            __syncthreads();
            if (t == 0) {
                int np  = g_nparts[c];
                int old = atomicAdd(&g_done2[c], 1);
                sflag = (old == np - 1);
                if (sflag) g_done2[c] = 0;        // reset for replay
            }
            __syncthreads();
            if (sflag) {
                float4 sa = __ldcg((const float4*)gs + t);
                float4 sb = __ldcg((const float4*)gs + t + 128);
                ((float4*)gs)[t]       = make_float4(0.f,0.f,0.f,0.f);
                ((float4*)gs)[t + 128] = make_float4(0.f,0.f,0.f,0.f);
                epilogue(c, cnt, t, sa, sb, ci4, cs4, sred);
            }
        }
    }

    // ---- chip-level finalize: all GRID blocks arrive ----
    if (t == 0) {
        __threadfence();
        if (atomicAdd(&g_done, 1) == GRID - 1) {
            float L  = atomicAdd(&g_loss, 0.0f);       // L2-coherent read
            int   np = atomicAdd(&g_present, 0);
            out[0] = L / (float)(np > 0 ? np : 1);
            g_done = 0; g_loss = 0.0f; g_present = 0;  // reset for replay
            __threadfence();
        }
    }
}

extern "C" void kernel_launch(void* const* d_in, const int* in_sizes, int n_in,
                              void* d_out, int out_size) {
    const float4* x4  = (const float4*)d_in[0];
    const float4* ci4 = (const float4*)d_in[1];
    const float4* cs4 = (const float4*)d_in[2];
    const void*   l   = d_in[3];

    k_scatter<<<32, 1024>>>((const int*)l, (const long long*)l);
    k_main<<<GRID, 128>>>(x4, ci4, cs4, (float*)d_out);
}